// round 11
// baseline (speedup 1.0000x reference)
#include <cuda_runtime.h>
#include <cuda_bf16.h>
#include <cstdint>

#define BATCH 16
#define SEQ   2048
#define DIM   128
#define TILE  128
#define TJ    64
#define NT    (SEQ/TILE)
#define NJ    (SEQ/TJ)
#define SCALE 0.088388347648318447f
#define LDE   136                 // bf16 elements per padded smem row
#define NELEM (BATCH*SEQ*DIM)

// element offsets (bf16) in smem
#define K_HI   0
#define K_LO   17408
#define QB_HI(p) (34816 + (p)*34816)
#define QB_LO(p) (43520 + (p)*34816)
#define VB_HI(p) (52224 + (p)*34816)
#define VB_LO(p) (60928 + (p)*34816)
#define SSL_BYTE 208896           // 256 floats row sums
#define SMEM_BYTES (208896 + 1024)

// pre-split bf16 inputs: [0]=Q, [1]=K, [2]=V
static __device__ __nv_bfloat16 g_hi[3][NELEM];
static __device__ __nv_bfloat16 g_lo[3][NELEM];

__device__ __forceinline__ uint32_t smem_u32(const void* p) {
    uint32_t a;
    asm("{ .reg .u64 t; cvta.to.shared.u64 t, %1; cvt.u32.u64 %0, t; }" : "=r"(a) : "l"(p));
    return a;
}
__device__ __forceinline__ void cpa16(uint32_t dst, const void* src) {
    asm volatile("cp.async.cg.shared.global [%0], [%1], 16;" :: "r"(dst), "l"(src));
}
__device__ __forceinline__ void cpa_commit() {
    asm volatile("cp.async.commit_group;" ::: "memory");
}
__device__ __forceinline__ void cpa_wait_all() {
    asm volatile("cp.async.wait_group 0;" ::: "memory");
}
__device__ __forceinline__ void ldsm4(uint32_t* r, uint32_t addr) {
    asm volatile("ldmatrix.sync.aligned.m8n8.x4.shared.b16 {%0,%1,%2,%3}, [%4];"
                 : "=r"(r[0]), "=r"(r[1]), "=r"(r[2]), "=r"(r[3]) : "r"(addr));
}
__device__ __forceinline__ void ldsm4t(uint32_t* r, uint32_t addr) {
    asm volatile("ldmatrix.sync.aligned.m8n8.x4.trans.shared.b16 {%0,%1,%2,%3}, [%4];"
                 : "=r"(r[0]), "=r"(r[1]), "=r"(r[2]), "=r"(r[3]) : "r"(addr));
}
__device__ __forceinline__ void mma16816(float* d, const uint32_t* a, const uint32_t* b) {
    asm volatile("mma.sync.aligned.m16n8k16.row.col.f32.bf16.bf16.f32 "
                 "{%0,%1,%2,%3}, {%4,%5,%6,%7}, {%8,%9}, {%0,%1,%2,%3};"
                 : "+f"(d[0]), "+f"(d[1]), "+f"(d[2]), "+f"(d[3])
                 : "r"(a[0]), "r"(a[1]), "r"(a[2]), "r"(a[3]), "r"(b[0]), "r"(b[1]));
}
__device__ __forceinline__ uint32_t pack_bf2(float a, float b) {
    __nv_bfloat162 t = __floats2bfloat162_rn(a, b);
    return *(uint32_t*)&t;
}
// P tile (128 rows x 64 bf16 cols) byte offset with XOR swizzle
__device__ __forceinline__ uint32_t pswz(int row, int col) {
    uint32_t byte = ((uint32_t)row << 7) + ((uint32_t)col << 1);
    return byte ^ (((uint32_t)row & 7u) << 4);
}

// ---------------- pre-pass: split fp32 -> bf16 hi/lo ----------------
__global__ __launch_bounds__(256)
void split_pre_kernel(const float* __restrict__ Q, const float* __restrict__ K,
                      const float* __restrict__ V) {
    const int t = blockIdx.y;
    const float* X = (t == 0) ? Q : ((t == 1) ? K : V);
    const size_t i4 = (size_t)blockIdx.x * blockDim.x + threadIdx.x;
    const float4 v = ((const float4*)X)[i4];
    __nv_bfloat162 h0 = __floats2bfloat162_rn(v.x, v.y);
    __nv_bfloat162 h1 = __floats2bfloat162_rn(v.z, v.w);
    __nv_bfloat162 l0 = __floats2bfloat162_rn(v.x - __bfloat162float(h0.x),
                                              v.y - __bfloat162float(h0.y));
    __nv_bfloat162 l1 = __floats2bfloat162_rn(v.z - __bfloat162float(h1.x),
                                              v.w - __bfloat162float(h1.y));
    uint2 hh, ll;
    hh.x = *(uint32_t*)&h0; hh.y = *(uint32_t*)&h1;
    ll.x = *(uint32_t*)&l0; ll.y = *(uint32_t*)&l1;
    ((uint2*)g_hi[t])[i4] = hh;
    ((uint2*)g_lo[t])[i4] = ll;
}

// ---------------- main kernel: pipelined TJ=64 chunks ----------------
__global__ __launch_bounds__(512, 1)
void attn_mma_kernel(float* __restrict__ outp, float* __restrict__ wts) {
    extern __shared__ __align__(16) char smem_raw[];
    __nv_bfloat16* sb = (__nv_bfloat16*)smem_raw;
    float* sL = (float*)(smem_raw + SSL_BYTE);   // [2][128]
    const uint32_t su = smem_u32(smem_raw);

    const int tid = threadIdx.x;
    const int wid = tid >> 5;               // 0..15
    const int l   = tid & 31;
    const int m   = wid & 7;
    const int h   = wid >> 3;
    const int m0  = m * 16;
    const int cpair = blockIdx.x;
    const int b   = blockIdx.y;

    const int g   = l >> 3, r = l & 7;
    const int gb0 = g & 1, gb1 = g >> 1;
    const int ar  = l >> 2, ac = l & 3;

    const int offA = (m0 + gb0 * 8 + r) * LDE + gb1 * 8;   // K A-frags
    // QV prefetch decomposition: 64 rows, per thread 16 elems (2 chunks) per tile
    const int prow = tid >> 3;              // 0..63
    const int pcol = (tid & 7) * 16;        // element col

    #pragma unroll 1
    for (int ph = 0; ph < 2; ph++) {
        const int it = ph ? (NT - 1 - cpair) : cpair;
        const int i0 = it * TILE;
        const int gi0 = i0 + m0 + ar;

        __syncthreads();   // smem reuse across phases

        // ---- K tile cp.async (128 rows, hi+lo) ----
        {
            const size_t base = (size_t)(b * SEQ + i0) * DIM;
            #pragma unroll
            for (int i = 0; i < 2; i++) {
                const int row = prow + i * 64;
                const uint32_t ds = su + (uint32_t)((row * LDE + pcol) << 1);
                const size_t go = base + (size_t)row * DIM + pcol;
                cpa16(ds + (K_HI << 1),      g_hi[1] + go);
                cpa16(ds + (K_HI << 1) + 16, g_hi[1] + go + 8);
                cpa16(ds + (K_LO << 1),      g_lo[1] + go);
                cpa16(ds + (K_LO << 1) + 16, g_lo[1] + go + 8);
            }
        }
        // ---- first QV chunk (j0 = i0) into buf 0 ----
        {
            const size_t base = (size_t)(b * SEQ + i0) * DIM;
            const uint32_t ds = su + (uint32_t)((prow * LDE + pcol) << 1);
            const size_t go = base + (size_t)prow * DIM + pcol;
            cpa16(ds + (QB_HI(0) << 1),      g_hi[0] + go);
            cpa16(ds + (QB_HI(0) << 1) + 16, g_hi[0] + go + 8);
            cpa16(ds + (QB_LO(0) << 1),      g_lo[0] + go);
            cpa16(ds + (QB_LO(0) << 1) + 16, g_lo[0] + go + 8);
            cpa16(ds + (VB_HI(0) << 1),      g_hi[2] + go);
            cpa16(ds + (VB_HI(0) << 1) + 16, g_hi[2] + go + 8);
            cpa16(ds + (VB_LO(0) << 1),      g_lo[2] + go);
            cpa16(ds + (VB_LO(0) << 1) + 16, g_lo[2] + go + 8);
            cpa_commit();
        }

        // ---- zero-fill lower-triangle cols [0, i0) (overlaps loads) ----
        {
            const int W0 = i0 / 4;
            const float4 z4 = make_float4(0.0f, 0.0f, 0.0f, 0.0f);
            for (int row = wid; row < TILE; row += 16) {
                float4* wr = (float4*)(wts + ((size_t)(b * SEQ + i0 + row)) * SEQ);
                for (int q = l; q < W0; q += 32) wr[q] = z4;
            }
        }

        float Oa[8][4];
        #pragma unroll
        for (int nb = 0; nb < 8; nb++)
            #pragma unroll
            for (int e = 0; e < 4; e++) Oa[nb][e] = 0.0f;
        float ls0 = 0.0f, ls1 = 0.0f;

        cpa_wait_all();
        __syncthreads();

        int buf = 0;
        const int jt0 = it * 2;             // first 64-chunk index
        #pragma unroll 1
        for (int jc = jt0; jc < NJ; jc++) {
            const int j0 = jc * TJ;
            const uint32_t qh = QB_HI(buf), ql = QB_LO(buf);
            const uint32_t vh = VB_HI(buf), vl = VB_LO(buf);

            // ---- MMA1: S(16x32 half) = Khi*Qhi + Klo*Qhi + Khi*Qlo ----
            float S[4][4];
            #pragma unroll
            for (int nb = 0; nb < 4; nb++)
                #pragma unroll
                for (int e = 0; e < 4; e++) S[nb][e] = 0.0f;

            #pragma unroll
            for (int ks = 0; ks < 8; ks++) {
                uint32_t ah[4], al[4];
                ldsm4(ah, su + (uint32_t)((K_HI + offA + ks * 16) << 1));
                ldsm4(al, su + (uint32_t)((K_LO + offA + ks * 16) << 1));
                #pragma unroll
                for (int nbp = 0; nbp < 2; nbp++) {
                    const int boff = ((h * 2 + nbp) * 16 + gb1 * 8 + r) * LDE + ks * 16 + gb0 * 8;
                    uint32_t bh[4], bl[4];
                    ldsm4(bh, su + (uint32_t)((qh + boff) << 1));
                    ldsm4(bl, su + (uint32_t)((ql + boff) << 1));
                    mma16816(S[2 * nbp],     ah, bh);
                    mma16816(S[2 * nbp + 1], ah, bh + 2);
                    mma16816(S[2 * nbp],     al, bh);
                    mma16816(S[2 * nbp + 1], al, bh + 2);
                    mma16816(S[2 * nbp],     ah, bl);
                    mma16816(S[2 * nbp + 1], ah, bl + 2);
                }
            }
            __syncthreads();   // Q reads done; P staging may overwrite Q buf

            // ---- prefetch next chunk into buf^1 (overlaps epilogue+MMA2) ----
            const bool more = (jc + 1 < NJ);
            if (more) {
                const int nb_ = buf ^ 1;
                const size_t base = (size_t)(b * SEQ + (jc + 1) * TJ) * DIM;
                const uint32_t ds = su + (uint32_t)((prow * LDE + pcol) << 1);
                const size_t go = base + (size_t)prow * DIM + pcol;
                cpa16(ds + (QB_HI(nb_) << 1),      g_hi[0] + go);
                cpa16(ds + (QB_HI(nb_) << 1) + 16, g_hi[0] + go + 8);
                cpa16(ds + (QB_LO(nb_) << 1),      g_lo[0] + go);
                cpa16(ds + (QB_LO(nb_) << 1) + 16, g_lo[0] + go + 8);
                cpa16(ds + (VB_HI(nb_) << 1),      g_hi[2] + go);
                cpa16(ds + (VB_HI(nb_) << 1) + 16, g_hi[2] + go + 8);
                cpa16(ds + (VB_LO(nb_) << 1),      g_lo[2] + go);
                cpa16(ds + (VB_LO(nb_) << 1) + 16, g_lo[2] + go + 8);
                cpa_commit();
            }

            // ---- epilogue: exp, mask, STG weights, stage P (swizzled) ----
            const bool diag = (j0 < i0 + TILE);
            const int cb = h * 32 + 2 * ac;
            float* wr0 = wts + ((size_t)(b * SEQ + gi0)) * SEQ + j0 + cb;
            float* wr1 = wr0 + (size_t)8 * SEQ;
            const uint32_t phb = su + (qh << 1);   // P_hi base (bytes)
            const uint32_t plb = su + (ql << 1);   // P_lo base (bytes)
            #pragma unroll
            for (int nb = 0; nb < 4; nb++) {
                float p0 = __expf(S[nb][0] * SCALE);
                float p1 = __expf(S[nb][1] * SCALE);
                float p2 = __expf(S[nb][2] * SCALE);
                float p3 = __expf(S[nb][3] * SCALE);
                const int j = j0 + cb + nb * 8;
                if (diag) {
                    if (j     < gi0)     p0 = 0.0f;
                    if (j + 1 < gi0)     p1 = 0.0f;
                    if (j     < gi0 + 8) p2 = 0.0f;
                    if (j + 1 < gi0 + 8) p3 = 0.0f;
                }
                ls0 += p0 + p1;
                ls1 += p2 + p3;
                *(float2*)(wr0 + nb * 8) = make_float2(p0, p1);
                *(float2*)(wr1 + nb * 8) = make_float2(p2, p3);
                const uint32_t h01 = pack_bf2(p0, p1);
                const uint32_t h23 = pack_bf2(p2, p3);
                __nv_bfloat162 hh01 = *(__nv_bfloat162*)&h01;
                __nv_bfloat162 hh23 = *(__nv_bfloat162*)&h23;
                const uint32_t l01 = pack_bf2(p0 - __bfloat162float(hh01.x),
                                              p1 - __bfloat162float(hh01.y));
                const uint32_t l23 = pack_bf2(p2 - __bfloat162float(hh23.x),
                                              p3 - __bfloat162float(hh23.y));
                const uint32_t o0 = pswz(m0 + ar,     cb + nb * 8);
                const uint32_t o1 = pswz(m0 + ar + 8, cb + nb * 8);
                *(uint32_t*)(smem_raw + (phb - su) + o0) = h01;
                *(uint32_t*)(smem_raw + (phb - su) + o1) = h23;
                *(uint32_t*)(smem_raw + (plb - su) + o0) = l01;
                *(uint32_t*)(smem_raw + (plb - su) + o1) = l23;
            }
            __syncthreads();   // P visible to all warps

            // ---- MMA2: O(16 x 64 d-half) += Phi*Vhi + Plo*Vhi + Phi*Vlo ----
            #pragma unroll
            for (int kb = 0; kb < 4; kb++) {
                uint32_t aPh[4], aPl[4];
                const uint32_t po = pswz(m0 + gb0 * 8 + r, kb * 16 + gb1 * 8);
                ldsm4(aPh, phb + po);
                ldsm4(aPl, plb + po);
                #pragma unroll
                for (int dbp = 0; dbp < 4; dbp++) {
                    const int voff = (kb * 16 + gb0 * 8 + r) * LDE + h * 64 + dbp * 16 + gb1 * 8;
                    uint32_t bh[4], bl[4];
                    ldsm4t(bh, su + (uint32_t)((vh + voff) << 1));
                    ldsm4t(bl, su + (uint32_t)((vl + voff) << 1));
                    mma16816(Oa[2 * dbp],     aPh, bh);
                    mma16816(Oa[2 * dbp + 1], aPh, bh + 2);
                    mma16816(Oa[2 * dbp],     aPl, bh);
                    mma16816(Oa[2 * dbp + 1], aPl, bh + 2);
                    mma16816(Oa[2 * dbp],     aPh, bl);
                    mma16816(Oa[2 * dbp + 1], aPh, bl + 2);
                }
            }

            if (more) cpa_wait_all();
            __syncthreads();   // MMA2 reads done; next iter may use buf^1, P buf free
            buf ^= 1;
        }

        // ---- reduce half-row sums; publish ----
        ls0 += __shfl_xor_sync(0xffffffffu, ls0, 1);
        ls0 += __shfl_xor_sync(0xffffffffu, ls0, 2);
        ls1 += __shfl_xor_sync(0xffffffffu, ls1, 1);
        ls1 += __shfl_xor_sync(0xffffffffu, ls1, 2);
        if (ac == 0) {
            sL[h * 128 + m0 + ar]     = ls0;
            sL[h * 128 + m0 + ar + 8] = ls1;
        }
        __syncthreads();

        const float inv0 = 1.0f / (sL[m0 + ar]     + sL[128 + m0 + ar]);
        const float inv1 = 1.0f / (sL[m0 + ar + 8] + sL[128 + m0 + ar + 8]);

        // ---- store normalized O ----
        float* or0 = outp + ((size_t)(b * SEQ + gi0)) * DIM + h * 64 + 2 * ac;
        float* or1 = or0 + 8 * DIM;
        #pragma unroll
        for (int nb = 0; nb < 8; nb++) {
            const int col = (nb >> 1) * 16 + (nb & 1) * 8;
            *(float2*)(or0 + col) = make_float2(Oa[nb][0] * inv0, Oa[nb][1] * inv0);
            *(float2*)(or1 + col) = make_float2(Oa[nb][2] * inv1, Oa[nb][3] * inv1);
        }

        // ---- in-kernel finalize: rescale own rows, cols [i0, SEQ) ----
        {
            const int W1 = (SEQ - i0) / 4;
            for (int row = wid; row < TILE; row += 16) {
                const float inv = 1.0f / (sL[row] + sL[128 + row]);
                float4* wr = (float4*)(wts + ((size_t)(b * SEQ + i0 + row)) * SEQ + i0);
                for (int q = l; q < W1; q += 32) {
                    float4 w = wr[q];
                    w.x *= inv; w.y *= inv; w.z *= inv; w.w *= inv;
                    wr[q] = w;
                }
            }
        }
    }
}

extern "C" void kernel_launch(void* const* d_in, const int* in_sizes, int n_in,
                              void* d_out, int out_size) {
    const float* Q = (const float*)d_in[0];
    const float* K = (const float*)d_in[1];
    const float* V = (const float*)d_in[2];
    float* outp = (float*)d_out;
    float* wts  = outp + (size_t)BATCH * SEQ * DIM;

    dim3 pgrid(NELEM / 4 / 256, 3);
    split_pre_kernel<<<pgrid, 256>>>(Q, K, V);

    cudaFuncSetAttribute(attn_mma_kernel,
                         cudaFuncAttributeMaxDynamicSharedMemorySize, SMEM_BYTES);
    dim3 grid(NT / 2, BATCH);
    attn_mma_kernel<<<grid, 512, SMEM_BYTES>>>(outp, wts);
}

// round 12
// speedup vs baseline: 1.0088x; 1.0088x over previous
#include <cuda_runtime.h>
#include <cuda_bf16.h>
#include <cstdint>

#define BATCH 16
#define SEQ   2048
#define DIM   128
#define TILE  128
#define TJ    64
#define NT    (SEQ/TILE)
#define NJ    (SEQ/TJ)
#define SCALE 0.088388347648318447f
#define NELEM (BATCH*SEQ*DIM)

// smem byte offsets: unpadded XOR-swizzled tiles (256B rows for 128-col tiles)
#define K_HI   0
#define K_LO   32768
#define Q_HI(p) (65536  + (p)*32768)
#define Q_LO(p) (81920  + (p)*32768)
#define V_HI(p) (131072 + (p)*32768)
#define V_LO(p) (147456 + (p)*32768)
#define P_HI   196608
#define P_LO   212992
#define SSL    229376              // 256 floats row sums
#define SMEM_BYTES (229376 + 1024)

// pre-split bf16 inputs: [0]=Q, [1]=K, [2]=V
static __device__ __nv_bfloat16 g_hi[3][NELEM];
static __device__ __nv_bfloat16 g_lo[3][NELEM];

__device__ __forceinline__ uint32_t smem_u32(const void* p) {
    uint32_t a;
    asm("{ .reg .u64 t; cvta.to.shared.u64 t, %1; cvt.u32.u64 %0, t; }" : "=r"(a) : "l"(p));
    return a;
}
__device__ __forceinline__ void cpa16(uint32_t dst, const void* src) {
    asm volatile("cp.async.cg.shared.global [%0], [%1], 16;" :: "r"(dst), "l"(src));
}
__device__ __forceinline__ void cpa_commit() {
    asm volatile("cp.async.commit_group;" ::: "memory");
}
__device__ __forceinline__ void cpa_wait_all() {
    asm volatile("cp.async.wait_group 0;" ::: "memory");
}
__device__ __forceinline__ void cpa_wait_1() {
    asm volatile("cp.async.wait_group 1;" ::: "memory");
}
__device__ __forceinline__ void ldsm4(uint32_t* r, uint32_t addr) {
    asm volatile("ldmatrix.sync.aligned.m8n8.x4.shared.b16 {%0,%1,%2,%3}, [%4];"
                 : "=r"(r[0]), "=r"(r[1]), "=r"(r[2]), "=r"(r[3]) : "r"(addr));
}
__device__ __forceinline__ void ldsm4t(uint32_t* r, uint32_t addr) {
    asm volatile("ldmatrix.sync.aligned.m8n8.x4.trans.shared.b16 {%0,%1,%2,%3}, [%4];"
                 : "=r"(r[0]), "=r"(r[1]), "=r"(r[2]), "=r"(r[3]) : "r"(addr));
}
__device__ __forceinline__ void mma16816(float* d, const uint32_t* a, const uint32_t* b) {
    asm volatile("mma.sync.aligned.m16n8k16.row.col.f32.bf16.bf16.f32 "
                 "{%0,%1,%2,%3}, {%4,%5,%6,%7}, {%8,%9}, {%0,%1,%2,%3};"
                 : "+f"(d[0]), "+f"(d[1]), "+f"(d[2]), "+f"(d[3])
                 : "r"(a[0]), "r"(a[1]), "r"(a[2]), "r"(a[3]), "r"(b[0]), "r"(b[1]));
}
__device__ __forceinline__ uint32_t pack_bf2(float a, float b) {
    __nv_bfloat162 t = __floats2bfloat162_rn(a, b);
    return *(uint32_t*)&t;
}
// 128-col tile (256B rows): XOR bits[6:4] with row[2:0] -> conflict-free ldsm
__device__ __forceinline__ uint32_t swzK(int row, int col) {
    uint32_t byte = ((uint32_t)row << 8) + ((uint32_t)col << 1);
    return byte ^ (((uint32_t)row & 7u) << 4);
}
// 64-col P tile (128B rows)
__device__ __forceinline__ uint32_t pswz(int row, int col) {
    uint32_t byte = ((uint32_t)row << 7) + ((uint32_t)col << 1);
    return byte ^ (((uint32_t)row & 7u) << 4);
}

// ---------------- pre-pass: split fp32 -> bf16 hi/lo ----------------
__global__ __launch_bounds__(256)
void split_pre_kernel(const float* __restrict__ Q, const float* __restrict__ K,
                      const float* __restrict__ V) {
    const int t = blockIdx.y;
    const float* X = (t == 0) ? Q : ((t == 1) ? K : V);
    const size_t i4 = (size_t)blockIdx.x * blockDim.x + threadIdx.x;
    const float4 v = ((const float4*)X)[i4];
    __nv_bfloat162 h0 = __floats2bfloat162_rn(v.x, v.y);
    __nv_bfloat162 h1 = __floats2bfloat162_rn(v.z, v.w);
    __nv_bfloat162 l0 = __floats2bfloat162_rn(v.x - __bfloat162float(h0.x),
                                              v.y - __bfloat162float(h0.y));
    __nv_bfloat162 l1 = __floats2bfloat162_rn(v.z - __bfloat162float(h1.x),
                                              v.w - __bfloat162float(h1.y));
    uint2 hh, ll;
    hh.x = *(uint32_t*)&h0; hh.y = *(uint32_t*)&h1;
    ll.x = *(uint32_t*)&l0; ll.y = *(uint32_t*)&l1;
    ((uint2*)g_hi[t])[i4] = hh;
    ((uint2*)g_lo[t])[i4] = ll;
}

// ---------------- main kernel ----------------
__global__ __launch_bounds__(512, 1)
void attn_mma_kernel(float* __restrict__ outp, float* __restrict__ wts) {
    extern __shared__ __align__(16) char smem[];
    float* sL = (float*)(smem + SSL);       // [2][128]
    const uint32_t su = smem_u32(smem);

    const int tid = threadIdx.x;
    const int wid = tid >> 5;               // 0..15
    const int l   = tid & 31;
    const int m   = wid & 7;
    const int h   = wid >> 3;
    const int m0  = m * 16;
    const int cpair = blockIdx.x;
    const int b   = blockIdx.y;

    const int g   = l >> 3, r = l & 7;
    const int gb0 = g & 1, gb1 = g >> 1;
    const int ar  = l >> 2, ac = l & 3;

    // 64-row tile prefetch decomposition: 2 consecutive 16B chunks / thread / tile
    const int prow = tid >> 3;              // 0..63
    const int pcol = (tid & 7) * 16;        // element col

    #pragma unroll 1
    for (int ph = 0; ph < 2; ph++) {
        const int it = ph ? (NT - 1 - cpair) : cpair;
        const int i0 = it * TILE;
        const int gi0 = i0 + m0 + ar;
        const int jt0 = it * 2;

        __syncthreads();   // smem reuse across phases

        // ---- prologue: K (128 rows) + Q0 + V0 cp.async, one group ----
        {
            const size_t kb = (size_t)(b * SEQ + i0) * DIM;
            #pragma unroll
            for (int i = 0; i < 2; i++) {
                const int row = prow + i * 64;
                const size_t go = kb + (size_t)row * DIM + pcol;
                const uint32_t d0 = swzK(row, pcol);
                const uint32_t d1 = swzK(row, pcol + 8);
                cpa16(su + K_HI + d0, g_hi[1] + go);
                cpa16(su + K_HI + d1, g_hi[1] + go + 8);
                cpa16(su + K_LO + d0, g_lo[1] + go);
                cpa16(su + K_LO + d1, g_lo[1] + go + 8);
            }
            const size_t qb = (size_t)(b * SEQ + jt0 * TJ) * DIM;
            const size_t go = qb + (size_t)prow * DIM + pcol;
            const uint32_t d0 = swzK(prow, pcol);
            const uint32_t d1 = swzK(prow, pcol + 8);
            const int p0 = jt0 & 1;
            cpa16(su + Q_HI(p0) + d0, g_hi[0] + go);
            cpa16(su + Q_HI(p0) + d1, g_hi[0] + go + 8);
            cpa16(su + Q_LO(p0) + d0, g_lo[0] + go);
            cpa16(su + Q_LO(p0) + d1, g_lo[0] + go + 8);
            cpa16(su + V_HI(p0) + d0, g_hi[2] + go);
            cpa16(su + V_HI(p0) + d1, g_hi[2] + go + 8);
            cpa16(su + V_LO(p0) + d0, g_lo[2] + go);
            cpa16(su + V_LO(p0) + d1, g_lo[2] + go + 8);
            cpa_commit();
        }

        // ---- zero-fill lower-triangle cols [0, i0) (overlaps loads) ----
        {
            const int W0 = i0 / 4;
            const float4 z4 = make_float4(0.0f, 0.0f, 0.0f, 0.0f);
            for (int row = wid; row < TILE; row += 16) {
                float4* wr = (float4*)(wts + ((size_t)(b * SEQ + i0 + row)) * SEQ);
                for (int q = l; q < W0; q += 32) wr[q] = z4;
            }
        }

        cpa_wait_all();
        __syncthreads();

        float Oa[8][4];
        #pragma unroll
        for (int nb = 0; nb < 8; nb++)
            #pragma unroll
            for (int e = 0; e < 4; e++) Oa[nb][e] = 0.0f;
        float ls0 = 0.0f, ls1 = 0.0f;

        #pragma unroll 1
        for (int jc = jt0; jc < NJ; jc++) {
            const int j0  = jc * TJ;
            const int buf = jc & 1;

            // ======== PHASE A: issue Q(jc+1); MMA1(jc); MMA2(jc-1) ========
            if (jc + 1 < NJ) {
                const int nb_ = buf ^ 1;
                const size_t go = (size_t)(b * SEQ + (jc + 1) * TJ) * DIM
                                + (size_t)prow * DIM + pcol;
                const uint32_t d0 = swzK(prow, pcol);
                const uint32_t d1 = swzK(prow, pcol + 8);
                cpa16(su + Q_HI(nb_) + d0, g_hi[0] + go);
                cpa16(su + Q_HI(nb_) + d1, g_hi[0] + go + 8);
                cpa16(su + Q_LO(nb_) + d0, g_lo[0] + go);
                cpa16(su + Q_LO(nb_) + d1, g_lo[0] + go + 8);
                cpa_commit();
            }

            // MMA1(jc): S(16x32 half) = Khi*Qhi + Klo*Qhi + Khi*Qlo
            float S[4][4];
            #pragma unroll
            for (int nb = 0; nb < 4; nb++)
                #pragma unroll
                for (int e = 0; e < 4; e++) S[nb][e] = 0.0f;
            #pragma unroll
            for (int ks = 0; ks < 8; ks++) {
                uint32_t ah[4], al[4];
                const uint32_t ao = swzK(m0 + gb0 * 8 + r, ks * 16 + gb1 * 8);
                ldsm4(ah, su + K_HI + ao);
                ldsm4(al, su + K_LO + ao);
                #pragma unroll
                for (int nbp = 0; nbp < 2; nbp++) {
                    const uint32_t bo = swzK(h * 32 + nbp * 16 + gb1 * 8 + r,
                                             ks * 16 + gb0 * 8);
                    uint32_t bh[4], bl[4];
                    ldsm4(bh, su + Q_HI(buf) + bo);
                    ldsm4(bl, su + Q_LO(buf) + bo);
                    mma16816(S[2 * nbp],     ah, bh);
                    mma16816(S[2 * nbp + 1], ah, bh + 2);
                    mma16816(S[2 * nbp],     al, bh);
                    mma16816(S[2 * nbp + 1], al, bh + 2);
                    mma16816(S[2 * nbp],     ah, bl);
                    mma16816(S[2 * nbp + 1], ah, bl + 2);
                }
            }

            // MMA2(jc-1): O += Phi*Vhi + Plo*Vhi + Phi*Vlo
            if (jc > jt0) {
                const int vb = buf ^ 1;
                #pragma unroll
                for (int kb = 0; kb < 4; kb++) {
                    uint32_t aPh[4], aPl[4];
                    const uint32_t po = pswz(m0 + gb0 * 8 + r, kb * 16 + gb1 * 8);
                    ldsm4(aPh, su + P_HI + po);
                    ldsm4(aPl, su + P_LO + po);
                    #pragma unroll
                    for (int dbp = 0; dbp < 4; dbp++) {
                        const uint32_t vo = swzK(kb * 16 + gb0 * 8 + r,
                                                 h * 64 + dbp * 16 + gb1 * 8);
                        uint32_t bh[4], bl[4];
                        ldsm4t(bh, su + V_HI(vb) + vo);
                        ldsm4t(bl, su + V_LO(vb) + vo);
                        mma16816(Oa[2 * dbp],     aPh, bh);
                        mma16816(Oa[2 * dbp + 1], aPh, bh + 2);
                        mma16816(Oa[2 * dbp],     aPl, bh);
                        mma16816(Oa[2 * dbp + 1], aPl, bh + 2);
                        mma16816(Oa[2 * dbp],     aPh, bl);
                        mma16816(Oa[2 * dbp + 1], aPh, bl + 2);
                    }
                }
            }
            __syncthreads();

            // ======== PHASE B: epilogue(jc); issue V(jc+1); wait ========
            const bool diag = (j0 < i0 + TILE);
            const int cb = h * 32 + 2 * ac;
            float* wr0 = wts + ((size_t)(b * SEQ + gi0)) * SEQ + j0 + cb;
            float* wr1 = wr0 + (size_t)8 * SEQ;
            #pragma unroll
            for (int nb = 0; nb < 4; nb++) {
                float p0 = __expf(S[nb][0] * SCALE);
                float p1 = __expf(S[nb][1] * SCALE);
                float p2 = __expf(S[nb][2] * SCALE);
                float p3 = __expf(S[nb][3] * SCALE);
                const int j = j0 + cb + nb * 8;
                if (diag) {
                    if (j     < gi0)     p0 = 0.0f;
                    if (j + 1 < gi0)     p1 = 0.0f;
                    if (j     < gi0 + 8) p2 = 0.0f;
                    if (j + 1 < gi0 + 8) p3 = 0.0f;
                }
                ls0 += p0 + p1;
                ls1 += p2 + p3;
                *(float2*)(wr0 + nb * 8) = make_float2(p0, p1);
                *(float2*)(wr1 + nb * 8) = make_float2(p2, p3);
                const uint32_t h01 = pack_bf2(p0, p1);
                const uint32_t h23 = pack_bf2(p2, p3);
                __nv_bfloat162 hh01 = *(__nv_bfloat162*)&h01;
                __nv_bfloat162 hh23 = *(__nv_bfloat162*)&h23;
                const uint32_t l01 = pack_bf2(p0 - __bfloat162float(hh01.x),
                                              p1 - __bfloat162float(hh01.y));
                const uint32_t l23 = pack_bf2(p2 - __bfloat162float(hh23.x),
                                              p3 - __bfloat162float(hh23.y));
                const uint32_t o0 = pswz(m0 + ar,     cb + nb * 8);
                const uint32_t o1 = pswz(m0 + ar + 8, cb + nb * 8);
                *(uint32_t*)(smem + P_HI + o0) = h01;
                *(uint32_t*)(smem + P_HI + o1) = h23;
                *(uint32_t*)(smem + P_LO + o0) = l01;
                *(uint32_t*)(smem + P_LO + o1) = l23;
            }
            if (jc + 1 < NJ) {
                const int nb_ = buf ^ 1;
                const size_t go = (size_t)(b * SEQ + (jc + 1) * TJ) * DIM
                                + (size_t)prow * DIM + pcol;
                const uint32_t d0 = swzK(prow, pcol);
                const uint32_t d1 = swzK(prow, pcol + 8);
                cpa16(su + V_HI(nb_) + d0, g_hi[2] + go);
                cpa16(su + V_HI(nb_) + d1, g_hi[2] + go + 8);
                cpa16(su + V_LO(nb_) + d0, g_lo[2] + go);
                cpa16(su + V_LO(nb_) + d1, g_lo[2] + go + 8);
                cpa_commit();
                cpa_wait_1();     // Q(jc+1) complete; only V(jc+1) may be pending
            }
            __syncthreads();
        }

        // ---- drain: MMA2(NJ-1) ----
        cpa_wait_all();
        __syncthreads();
        {
            const int vb = (NJ - 1) & 1;
            #pragma unroll
            for (int kb = 0; kb < 4; kb++) {
                uint32_t aPh[4], aPl[4];
                const uint32_t po = pswz(m0 + gb0 * 8 + r, kb * 16 + gb1 * 8);
                ldsm4(aPh, su + P_HI + po);
                ldsm4(aPl, su + P_LO + po);
                #pragma unroll
                for (int dbp = 0; dbp < 4; dbp++) {
                    const uint32_t vo = swzK(kb * 16 + gb0 * 8 + r,
                                             h * 64 + dbp * 16 + gb1 * 8);
                    uint32_t bh[4], bl[4];
                    ldsm4t(bh, su + V_HI(vb) + vo);
                    ldsm4t(bl, su + V_LO(vb) + vo);
                    mma16816(Oa[2 * dbp],     aPh, bh);
                    mma16816(Oa[2 * dbp + 1], aPh, bh + 2);
                    mma16816(Oa[2 * dbp],     aPl, bh);
                    mma16816(Oa[2 * dbp + 1], aPl, bh + 2);
                    mma16816(Oa[2 * dbp],     aPh, bl);
                    mma16816(Oa[2 * dbp + 1], aPh, bl + 2);
                }
            }
        }

        // ---- reduce half-row sums; publish ----
        ls0 += __shfl_xor_sync(0xffffffffu, ls0, 1);
        ls0 += __shfl_xor_sync(0xffffffffu, ls0, 2);
        ls1 += __shfl_xor_sync(0xffffffffu, ls1, 1);
        ls1 += __shfl_xor_sync(0xffffffffu, ls1, 2);
        if (ac == 0) {
            sL[h * 128 + m0 + ar]     = ls0;
            sL[h * 128 + m0 + ar + 8] = ls1;
        }
        __syncthreads();

        const float inv0 = 1.0f / (sL[m0 + ar]     + sL[128 + m0 + ar]);
        const float inv1 = 1.0f / (sL[m0 + ar + 8] + sL[128 + m0 + ar + 8]);

        // ---- store normalized O (this warp's d-half) ----
        float* or0 = outp + ((size_t)(b * SEQ + gi0)) * DIM + h * 64 + 2 * ac;
        float* or1 = or0 + 8 * DIM;
        #pragma unroll
        for (int nb = 0; nb < 8; nb++) {
            const int col = (nb >> 1) * 16 + (nb & 1) * 8;
            *(float2*)(or0 + col) = make_float2(Oa[nb][0] * inv0, Oa[nb][1] * inv0);
            *(float2*)(or1 + col) = make_float2(Oa[nb][2] * inv1, Oa[nb][3] * inv1);
        }

        // ---- in-kernel finalize: rescale own rows, cols [i0, SEQ) ----
        {
            const int W1 = (SEQ - i0) / 4;
            for (int row = wid; row < TILE; row += 16) {
                const float inv = 1.0f / (sL[row] + sL[128 + row]);
                float4* wr = (float4*)(wts + ((size_t)(b * SEQ + i0 + row)) * SEQ + i0);
                for (int q = l; q < W1; q += 32) {
                    float4 w = wr[q];
                    w.x *= inv; w.y *= inv; w.z *= inv; w.w *= inv;
                    wr[q] = w;
                }
            }
        }
    }
}

extern "C" void kernel_launch(void* const* d_in, const int* in_sizes, int n_in,
                              void* d_out, int out_size) {
    const float* Q = (const float*)d_in[0];
    const float* K = (const float*)d_in[1];
    const float* V = (const float*)d_in[2];
    float* outp = (float*)d_out;
    float* wts  = outp + (size_t)BATCH * SEQ * DIM;

    dim3 pgrid(NELEM / 4 / 256, 3);
    split_pre_kernel<<<pgrid, 256>>>(Q, K, V);

    cudaFuncSetAttribute(attn_mma_kernel,
                         cudaFuncAttributeMaxDynamicSharedMemorySize, SMEM_BYTES);
    dim3 grid(NT / 2, BATCH);
    attn_mma_kernel<<<grid, 512, SMEM_BYTES>>>(outp, wts);
}

// round 13
// speedup vs baseline: 1.2245x; 1.2139x over previous
#include <cuda_runtime.h>
#include <cuda_bf16.h>
#include <cuda_fp16.h>
#include <cstdint>

#define BATCH 16
#define SEQ   2048
#define DIM   128
#define TILE  128
#define NT    (SEQ/TILE)
#define SCALE 0.088388347648318447f
#define LDE   136                 // 16-bit elements per padded smem row
#define NELEM (BATCH*SEQ*DIM)

#define T_ELEMS (TILE*LDE)
#define OFF_KHI 0
#define OFF_KLO (1*T_ELEMS)
#define OFF_QHI (2*T_ELEMS)      /* reused as P(fp16) staging after MMA1 */
#define OFF_QLO (3*T_ELEMS)
#define OFF_V16 (4*T_ELEMS)
#define OFF_SL  (5*T_ELEMS)      // 256 floats: per-half row sums
#define SMEM_BYTES (5*T_ELEMS*2 + 256*4)

// pre-split bf16: [0]=Q, [1]=K ; V pre-converted to fp16
static __device__ __nv_bfloat16 g_hi[2][NELEM];
static __device__ __nv_bfloat16 g_lo[2][NELEM];
static __device__ __half       g_v16[NELEM];

__device__ __forceinline__ uint32_t smem_u32(const void* p) {
    uint32_t a;
    asm("{ .reg .u64 t; cvta.to.shared.u64 t, %1; cvt.u32.u64 %0, t; }" : "=r"(a) : "l"(p));
    return a;
}
__device__ __forceinline__ void cpa16(uint32_t dst, const void* src) {
    asm volatile("cp.async.cg.shared.global [%0], [%1], 16;" :: "r"(dst), "l"(src));
}
__device__ __forceinline__ void cpa_commit() {
    asm volatile("cp.async.commit_group;" ::: "memory");
}
__device__ __forceinline__ void cpa_wait_all() {
    asm volatile("cp.async.wait_group 0;" ::: "memory");
}
__device__ __forceinline__ void ldsm4(uint32_t* r, uint32_t addr) {
    asm volatile("ldmatrix.sync.aligned.m8n8.x4.shared.b16 {%0,%1,%2,%3}, [%4];"
                 : "=r"(r[0]), "=r"(r[1]), "=r"(r[2]), "=r"(r[3]) : "r"(addr));
}
__device__ __forceinline__ void ldsm4t(uint32_t* r, uint32_t addr) {
    asm volatile("ldmatrix.sync.aligned.m8n8.x4.trans.shared.b16 {%0,%1,%2,%3}, [%4];"
                 : "=r"(r[0]), "=r"(r[1]), "=r"(r[2]), "=r"(r[3]) : "r"(addr));
}
__device__ __forceinline__ void mma_bf16(float* d, const uint32_t* a, const uint32_t* b) {
    asm volatile("mma.sync.aligned.m16n8k16.row.col.f32.bf16.bf16.f32 "
                 "{%0,%1,%2,%3}, {%4,%5,%6,%7}, {%8,%9}, {%0,%1,%2,%3};"
                 : "+f"(d[0]), "+f"(d[1]), "+f"(d[2]), "+f"(d[3])
                 : "r"(a[0]), "r"(a[1]), "r"(a[2]), "r"(a[3]), "r"(b[0]), "r"(b[1]));
}
__device__ __forceinline__ void mma_f16(float* d, const uint32_t* a, const uint32_t* b) {
    asm volatile("mma.sync.aligned.m16n8k16.row.col.f32.f16.f16.f32 "
                 "{%0,%1,%2,%3}, {%4,%5,%6,%7}, {%8,%9}, {%0,%1,%2,%3};"
                 : "+f"(d[0]), "+f"(d[1]), "+f"(d[2]), "+f"(d[3])
                 : "r"(a[0]), "r"(a[1]), "r"(a[2]), "r"(a[3]), "r"(b[0]), "r"(b[1]));
}
__device__ __forceinline__ uint32_t pack_h2(float a, float b) {
    __half2 t = __floats2half2_rn(a, b);
    return *(uint32_t*)&t;
}

// split float4 into bf16 hi/lo, store 4 elements at element offsets ehi/elo
__device__ __forceinline__ void split_store(__nv_bfloat16* sb, int ehi, int elo, float4 v) {
    __nv_bfloat162 h0 = __floats2bfloat162_rn(v.x, v.y);
    __nv_bfloat162 h1 = __floats2bfloat162_rn(v.z, v.w);
    __nv_bfloat162 l0 = __floats2bfloat162_rn(v.x - __bfloat162float(h0.x),
                                              v.y - __bfloat162float(h0.y));
    __nv_bfloat162 l1 = __floats2bfloat162_rn(v.z - __bfloat162float(h1.x),
                                              v.w - __bfloat162float(h1.y));
    uint2 hh, ll;
    hh.x = *(uint32_t*)&h0; hh.y = *(uint32_t*)&h1;
    ll.x = *(uint32_t*)&l0; ll.y = *(uint32_t*)&l1;
    *(uint2*)(sb + ehi) = hh;
    *(uint2*)(sb + elo) = ll;
}

// ---------------- pre-pass: Q/K split bf16; V -> fp16 ----------------
__global__ __launch_bounds__(256)
void split_pre_kernel(const float* __restrict__ Q, const float* __restrict__ K,
                      const float* __restrict__ V) {
    const int t = blockIdx.y;
    const size_t i4 = (size_t)blockIdx.x * blockDim.x + threadIdx.x;
    if (t == 2) {
        const float4 v = ((const float4*)V)[i4];
        __half2 a = __floats2half2_rn(v.x, v.y);
        __half2 b = __floats2half2_rn(v.z, v.w);
        uint2 o; o.x = *(uint32_t*)&a; o.y = *(uint32_t*)&b;
        ((uint2*)g_v16)[i4] = o;
        return;
    }
    const float* X = (t == 0) ? Q : K;
    const float4 v = ((const float4*)X)[i4];
    __nv_bfloat162 h0 = __floats2bfloat162_rn(v.x, v.y);
    __nv_bfloat162 h1 = __floats2bfloat162_rn(v.z, v.w);
    __nv_bfloat162 l0 = __floats2bfloat162_rn(v.x - __bfloat162float(h0.x),
                                              v.y - __bfloat162float(h0.y));
    __nv_bfloat162 l1 = __floats2bfloat162_rn(v.z - __bfloat162float(h1.x),
                                              v.w - __bfloat162float(h1.y));
    uint2 hh, ll;
    hh.x = *(uint32_t*)&h0; hh.y = *(uint32_t*)&h1;
    ll.x = *(uint32_t*)&l0; ll.y = *(uint32_t*)&l1;
    ((uint2*)g_hi[t])[i4] = hh;
    ((uint2*)g_lo[t])[i4] = ll;
}

// ---------------- main kernel (R10 structure, fp16 PV, 9-bin schedule) ----------------
__global__ __launch_bounds__(512, 1)
void attn_mma_kernel(float* __restrict__ outp, float* __restrict__ wts) {
    extern __shared__ __align__(16) char smem_raw[];
    __nv_bfloat16* sb = (__nv_bfloat16*)smem_raw;
    float* sL = (float*)(sb + OFF_SL);      // [2][128]
    const uint32_t su = smem_u32(smem_raw);

    const int tid = threadIdx.x;
    const int wid = tid >> 5;               // 0..15
    const int l   = tid & 31;
    const int m   = wid & 7;
    const int h   = wid >> 3;
    const int m0  = m * 16;
    const int bin = blockIdx.x;             // 0..8
    const int b   = blockIdx.y;

    const int g   = l >> 3, r = l & 7;
    const int gb0 = g & 1, gb1 = g >> 1;
    const int ar  = l >> 2, ac = l & 3;

    const int offA = (m0 + gb0 * 8 + r) * LDE + gb1 * 8;
    const int offB = (gb1 * 8 + r) * LDE + gb0 * 8;
    const int offV = (gb0 * 8 + r) * LDE + gb1 * 8;

    const int crow0 = tid >> 4;             // 0..31
    const int ccol0 = (tid & 15) * 8;

    // 9-bin balanced schedule: bin0 -> {0}; bins1-7 -> {bin, 16-bin}; bin8 -> {8}
    const int itA = (bin == 0) ? 0 : bin;
    const int itB = (bin >= 1 && bin <= 7) ? (16 - bin) : -1;

    #pragma unroll 1
    for (int ph = 0; ph < 2; ph++) {
        const int it = ph ? itB : itA;
        if (it < 0) break;
        const int i0 = it * TILE;
        const int gi0 = i0 + m0 + ar;

        __syncthreads();   // smem reuse across phases

        // ---- K tile via cp.async ----
        {
            const size_t base = (size_t)(b * SEQ + i0) * DIM;
            #pragma unroll
            for (int i = 0; i < 4; i++) {
                const int row = crow0 + i * 32;
                const uint32_t ds = su + (uint32_t)((row * LDE + ccol0) << 1);
                const size_t gofs = base + (size_t)row * DIM + ccol0;
                cpa16(ds + (OFF_KHI << 1), g_hi[1] + gofs);
                cpa16(ds + (OFF_KLO << 1), g_lo[1] + gofs);
            }
            cpa_commit();
        }

        // ---- zero-fill lower-triangle cols [0, i0) ----
        {
            const int W0 = i0 / 4;
            const float4 z4 = make_float4(0.0f, 0.0f, 0.0f, 0.0f);
            for (int row = wid; row < TILE; row += 16) {
                float4* wr = (float4*)(wts + ((size_t)(b * SEQ + i0 + row)) * SEQ);
                for (int q = l; q < W0; q += 32) wr[q] = z4;
            }
        }

        float Oa[8][4];
        #pragma unroll
        for (int nb = 0; nb < 8; nb++)
            #pragma unroll
            for (int e = 0; e < 4; e++) Oa[nb][e] = 0.0f;
        float ls0 = 0.0f, ls1 = 0.0f;

        #pragma unroll 1
        for (int jt = it; jt < NT; jt++) {
            const int j0 = jt * TILE;
            __syncthreads();

            // ---- Q (hi/lo) + V (fp16) via cp.async ----
            {
                const size_t base = (size_t)(b * SEQ + j0) * DIM;
                #pragma unroll
                for (int i = 0; i < 4; i++) {
                    const int row = crow0 + i * 32;
                    const uint32_t ds = su + (uint32_t)((row * LDE + ccol0) << 1);
                    const size_t gofs = base + (size_t)row * DIM + ccol0;
                    cpa16(ds + (OFF_QHI << 1), g_hi[0] + gofs);
                    cpa16(ds + (OFF_QLO << 1), g_lo[0] + gofs);
                    cpa16(ds + (OFF_V16 << 1), g_v16 + gofs);
                }
                cpa_commit();
                cpa_wait_all();
            }
            __syncthreads();

            // ---- MMA1 (bf16): S = Khi*Qhi + Klo*Qhi + Khi*Qlo ----
            float S[8][4];
            #pragma unroll
            for (int nb = 0; nb < 8; nb++)
                #pragma unroll
                for (int e = 0; e < 4; e++) S[nb][e] = 0.0f;

            #pragma unroll
            for (int ks = 0; ks < 8; ks++) {
                uint32_t ah[4], al[4];
                ldsm4(ah, su + (uint32_t)((OFF_KHI + offA + ks * 16) << 1));
                ldsm4(al, su + (uint32_t)((OFF_KLO + offA + ks * 16) << 1));
                #pragma unroll
                for (int nbp = 0; nbp < 4; nbp++) {
                    const int nbg = h * 4 + nbp;
                    uint32_t bh[4], bl[4];
                    ldsm4(bh, su + (uint32_t)((OFF_QHI + offB + nbg * 16 * LDE + ks * 16) << 1));
                    ldsm4(bl, su + (uint32_t)((OFF_QLO + offB + nbg * 16 * LDE + ks * 16) << 1));
                    mma_bf16(S[2 * nbp],     ah, bh);
                    mma_bf16(S[2 * nbp + 1], ah, bh + 2);
                    mma_bf16(S[2 * nbp],     al, bh);
                    mma_bf16(S[2 * nbp + 1], al, bh + 2);
                    mma_bf16(S[2 * nbp],     ah, bl);
                    mma_bf16(S[2 * nbp + 1], ah, bl + 2);
                }
            }
            __syncthreads();   // Q reads done before P staging overwrites

            // ---- epilogue: exp, mask, STG weights, stage P (fp16) ----
            const bool diag = (jt == it);
            const int cb = h * 64 + 2 * ac;
            float* wr0 = wts + ((size_t)(b * SEQ + gi0)) * SEQ + j0 + cb;
            float* wr1 = wr0 + (size_t)8 * SEQ;
            #pragma unroll
            for (int nb = 0; nb < 8; nb++) {
                float p0 = __expf(S[nb][0] * SCALE);
                float p1 = __expf(S[nb][1] * SCALE);
                float p2 = __expf(S[nb][2] * SCALE);
                float p3 = __expf(S[nb][3] * SCALE);
                const int j = j0 + cb + nb * 8;
                if (diag) {
                    if (j     < gi0)     p0 = 0.0f;
                    if (j + 1 < gi0)     p1 = 0.0f;
                    if (j     < gi0 + 8) p2 = 0.0f;
                    if (j + 1 < gi0 + 8) p3 = 0.0f;
                }
                ls0 += p0 + p1;
                ls1 += p2 + p3;
                *(float2*)(wr0 + nb * 8) = make_float2(p0, p1);
                *(float2*)(wr1 + nb * 8) = make_float2(p2, p3);
                const int e0 = (m0 + ar) * LDE + cb + nb * 8;
                const int e1 = e0 + 8 * LDE;
                *(uint32_t*)(sb + OFF_QHI + e0) = pack_h2(p0, p1);
                *(uint32_t*)(sb + OFF_QHI + e1) = pack_h2(p2, p3);
            }
            __syncthreads();   // P staged; both halves visible

            // ---- MMA2 (fp16, single product): O += P * V ----
            #pragma unroll
            for (int kb = 0; kb < 8; kb++) {
                uint32_t aP[4];
                ldsm4(aP, su + (uint32_t)((OFF_QHI + offA + kb * 16) << 1));
                #pragma unroll
                for (int dbp = 0; dbp < 4; dbp++) {
                    const int dbg = h * 4 + dbp;
                    uint32_t bv[4];
                    ldsm4t(bv, su + (uint32_t)((OFF_V16 + offV + kb * 16 * LDE + dbg * 16) << 1));
                    mma_f16(Oa[2 * dbp],     aP, bv);
                    mma_f16(Oa[2 * dbp + 1], aP, bv + 2);
                }
            }
        }

        // ---- reduce half-row sums; publish ----
        ls0 += __shfl_xor_sync(0xffffffffu, ls0, 1);
        ls0 += __shfl_xor_sync(0xffffffffu, ls0, 2);
        ls1 += __shfl_xor_sync(0xffffffffu, ls1, 1);
        ls1 += __shfl_xor_sync(0xffffffffu, ls1, 2);
        if (ac == 0) {
            sL[h * 128 + m0 + ar]     = ls0;
            sL[h * 128 + m0 + ar + 8] = ls1;
        }
        __syncthreads();

        const float inv0 = 1.0f / (sL[m0 + ar]     + sL[128 + m0 + ar]);
        const float inv1 = 1.0f / (sL[m0 + ar + 8] + sL[128 + m0 + ar + 8]);

        // ---- store normalized O ----
        float* or0 = outp + ((size_t)(b * SEQ + gi0)) * DIM + h * 64 + 2 * ac;
        float* or1 = or0 + 8 * DIM;
        #pragma unroll
        for (int nb = 0; nb < 8; nb++) {
            *(float2*)(or0 + nb * 8) = make_float2(Oa[nb][0] * inv0, Oa[nb][1] * inv0);
            *(float2*)(or1 + nb * 8) = make_float2(Oa[nb][2] * inv1, Oa[nb][3] * inv1);
        }

        // ---- in-kernel finalize: rescale own rows, cols [i0, SEQ) ----
        {
            const int W1 = (SEQ - i0) / 4;
            for (int row = wid; row < TILE; row += 16) {
                const float inv = 1.0f / (sL[row] + sL[128 + row]);
                float4* wr = (float4*)(wts + ((size_t)(b * SEQ + i0 + row)) * SEQ + i0);
                for (int q = l; q < W1; q += 32) {
                    float4 w = wr[q];
                    w.x *= inv; w.y *= inv; w.z *= inv; w.w *= inv;
                    wr[q] = w;
                }
            }
        }
    }
}

extern "C" void kernel_launch(void* const* d_in, const int* in_sizes, int n_in,
                              void* d_out, int out_size) {
    const float* Q = (const float*)d_in[0];
    const float* K = (const float*)d_in[1];
    const float* V = (const float*)d_in[2];
    float* outp = (float*)d_out;
    float* wts  = outp + (size_t)BATCH * SEQ * DIM;

    dim3 pgrid(NELEM / 4 / 256, 3);
    split_pre_kernel<<<pgrid, 256>>>(Q, K, V);

    cudaFuncSetAttribute(attn_mma_kernel,
                         cudaFuncAttributeMaxDynamicSharedMemorySize, SMEM_BYTES);
    dim3 grid(9, BATCH);
    attn_mma_kernel<<<grid, 512, SMEM_BYTES>>>(outp, wts);
}

// round 14
// speedup vs baseline: 1.4498x; 1.1840x over previous
#include <cuda_runtime.h>
#include <cuda_bf16.h>
#include <cuda_fp16.h>
#include <cstdint>

#define BATCH 16
#define SEQ   2048
#define DIM   128
#define TILE  128
#define NT    (SEQ/TILE)
#define SCALE 0.088388347648318447f
#define LDE   136                 // 16-bit elements per padded smem row
#define NELEM (BATCH*SEQ*DIM)

#define T_ELEMS (TILE*LDE)
#define OFF_K   0
#define OFF_Q   (1*T_ELEMS)      /* reused as P(fp16) staging after MMA1 */
#define OFF_V   (2*T_ELEMS)
#define OFF_SL  (3*T_ELEMS)      // 256 floats: per-half row sums
#define SMEM_BYTES (3*T_ELEMS*2 + 256*4)

// pre-converted fp16 inputs
static __device__ __half g_q16[NELEM];
static __device__ __half g_k16[NELEM];
static __device__ __half g_v16[NELEM];

__device__ __forceinline__ uint32_t smem_u32(const void* p) {
    uint32_t a;
    asm("{ .reg .u64 t; cvta.to.shared.u64 t, %1; cvt.u32.u64 %0, t; }" : "=r"(a) : "l"(p));
    return a;
}
__device__ __forceinline__ void cpa16(uint32_t dst, const void* src) {
    asm volatile("cp.async.cg.shared.global [%0], [%1], 16;" :: "r"(dst), "l"(src));
}
__device__ __forceinline__ void cpa_commit() {
    asm volatile("cp.async.commit_group;" ::: "memory");
}
__device__ __forceinline__ void cpa_wait_all() {
    asm volatile("cp.async.wait_group 0;" ::: "memory");
}
__device__ __forceinline__ void ldsm4(uint32_t* r, uint32_t addr) {
    asm volatile("ldmatrix.sync.aligned.m8n8.x4.shared.b16 {%0,%1,%2,%3}, [%4];"
                 : "=r"(r[0]), "=r"(r[1]), "=r"(r[2]), "=r"(r[3]) : "r"(addr));
}
__device__ __forceinline__ void ldsm4t(uint32_t* r, uint32_t addr) {
    asm volatile("ldmatrix.sync.aligned.m8n8.x4.trans.shared.b16 {%0,%1,%2,%3}, [%4];"
                 : "=r"(r[0]), "=r"(r[1]), "=r"(r[2]), "=r"(r[3]) : "r"(addr));
}
__device__ __forceinline__ void mma_f16(float* d, const uint32_t* a, const uint32_t* b) {
    asm volatile("mma.sync.aligned.m16n8k16.row.col.f32.f16.f16.f32 "
                 "{%0,%1,%2,%3}, {%4,%5,%6,%7}, {%8,%9}, {%0,%1,%2,%3};"
                 : "+f"(d[0]), "+f"(d[1]), "+f"(d[2]), "+f"(d[3])
                 : "r"(a[0]), "r"(a[1]), "r"(a[2]), "r"(a[3]), "r"(b[0]), "r"(b[1]));
}
__device__ __forceinline__ uint32_t pack_h2(float a, float b) {
    __half2 t = __floats2half2_rn(a, b);
    return *(uint32_t*)&t;
}

// ---------------- pre-pass: Q/K/V -> fp16 ----------------
__global__ __launch_bounds__(256)
void conv_pre_kernel(const float* __restrict__ Q, const float* __restrict__ K,
                     const float* __restrict__ V) {
    const int t = blockIdx.y;
    const float* X = (t == 0) ? Q : ((t == 1) ? K : V);
    __half* D = (t == 0) ? g_q16 : ((t == 1) ? g_k16 : g_v16);
    const size_t i4 = (size_t)blockIdx.x * blockDim.x + threadIdx.x;
    const float4 v = ((const float4*)X)[i4];
    __half2 a = __floats2half2_rn(v.x, v.y);
    __half2 b = __floats2half2_rn(v.z, v.w);
    uint2 o; o.x = *(uint32_t*)&a; o.y = *(uint32_t*)&b;
    ((uint2*)D)[i4] = o;
}

// ---------------- main kernel ----------------
__global__ __launch_bounds__(512, 1)
void attn_mma_kernel(float* __restrict__ outp, float* __restrict__ wts) {
    extern __shared__ __align__(16) char smem_raw[];
    __half* sb = (__half*)smem_raw;
    float* sL = (float*)(sb + OFF_SL);      // [2][128]
    const uint32_t su = smem_u32(smem_raw);

    const int tid = threadIdx.x;
    const int wid = tid >> 5;               // 0..15
    const int l   = tid & 31;
    const int m   = wid & 7;
    const int h   = wid >> 3;
    const int m0  = m * 16;
    const int bin = blockIdx.x;             // 0..8
    const int b   = blockIdx.y;

    const int g   = l >> 3, r = l & 7;
    const int gb0 = g & 1, gb1 = g >> 1;
    const int ar  = l >> 2, ac = l & 3;

    const int offA = (m0 + gb0 * 8 + r) * LDE + gb1 * 8;
    const int offB = (gb1 * 8 + r) * LDE + gb0 * 8;
    const int offV = (gb0 * 8 + r) * LDE + gb1 * 8;

    const int crow0 = tid >> 4;             // 0..31
    const int ccol0 = (tid & 15) * 8;

    // 9-bin balanced schedule: bin0 -> {0}; bins1-7 -> {bin, 16-bin}; bin8 -> {8}
    const int itA = (bin == 0) ? 0 : bin;
    const int itB = (bin >= 1 && bin <= 7) ? (16 - bin) : -1;

    #pragma unroll 1
    for (int ph = 0; ph < 2; ph++) {
        const int it = ph ? itB : itA;
        if (it < 0) break;
        const int i0 = it * TILE;
        const int gi0 = i0 + m0 + ar;

        __syncthreads();   // smem reuse across phases

        // ---- K tile via cp.async ----
        {
            const size_t base = (size_t)(b * SEQ + i0) * DIM;
            #pragma unroll
            for (int i = 0; i < 4; i++) {
                const int row = crow0 + i * 32;
                const uint32_t ds = su + (uint32_t)((row * LDE + ccol0) << 1);
                cpa16(ds + (OFF_K << 1), g_k16 + base + (size_t)row * DIM + ccol0);
            }
            cpa_commit();
        }

        // ---- zero-fill lower-triangle cols [0, i0) ----
        {
            const int W0 = i0 / 4;
            const float4 z4 = make_float4(0.0f, 0.0f, 0.0f, 0.0f);
            for (int row = wid; row < TILE; row += 16) {
                float4* wr = (float4*)(wts + ((size_t)(b * SEQ + i0 + row)) * SEQ);
                for (int q = l; q < W0; q += 32) wr[q] = z4;
            }
        }

        float Oa[8][4];
        #pragma unroll
        for (int nb = 0; nb < 8; nb++)
            #pragma unroll
            for (int e = 0; e < 4; e++) Oa[nb][e] = 0.0f;
        float ls0 = 0.0f, ls1 = 0.0f;

        #pragma unroll 1
        for (int jt = it; jt < NT; jt++) {
            const int j0 = jt * TILE;
            __syncthreads();

            // ---- Q + V (fp16) via cp.async ----
            {
                const size_t base = (size_t)(b * SEQ + j0) * DIM;
                #pragma unroll
                for (int i = 0; i < 4; i++) {
                    const int row = crow0 + i * 32;
                    const uint32_t ds = su + (uint32_t)((row * LDE + ccol0) << 1);
                    const size_t gofs = base + (size_t)row * DIM + ccol0;
                    cpa16(ds + (OFF_Q << 1), g_q16 + gofs);
                    cpa16(ds + (OFF_V << 1), g_v16 + gofs);
                }
                cpa_commit();
                cpa_wait_all();
            }
            __syncthreads();

            // ---- MMA1 (fp16 single product): S = K . Q^T ----
            float S[8][4];
            #pragma unroll
            for (int nb = 0; nb < 8; nb++)
                #pragma unroll
                for (int e = 0; e < 4; e++) S[nb][e] = 0.0f;

            #pragma unroll
            for (int ks = 0; ks < 8; ks++) {
                uint32_t ak[4];
                ldsm4(ak, su + (uint32_t)((OFF_K + offA + ks * 16) << 1));
                #pragma unroll
                for (int nbp = 0; nbp < 4; nbp++) {
                    const int nbg = h * 4 + nbp;
                    uint32_t bq[4];
                    ldsm4(bq, su + (uint32_t)((OFF_Q + offB + nbg * 16 * LDE + ks * 16) << 1));
                    mma_f16(S[2 * nbp],     ak, bq);
                    mma_f16(S[2 * nbp + 1], ak, bq + 2);
                }
            }
            __syncthreads();   // Q reads done before P staging overwrites

            // ---- epilogue: exp, mask, STG weights, stage P (fp16) ----
            const bool diag = (jt == it);
            const int cb = h * 64 + 2 * ac;
            float* wr0 = wts + ((size_t)(b * SEQ + gi0)) * SEQ + j0 + cb;
            float* wr1 = wr0 + (size_t)8 * SEQ;
            #pragma unroll
            for (int nb = 0; nb < 8; nb++) {
                float p0 = __expf(S[nb][0] * SCALE);
                float p1 = __expf(S[nb][1] * SCALE);
                float p2 = __expf(S[nb][2] * SCALE);
                float p3 = __expf(S[nb][3] * SCALE);
                const int j = j0 + cb + nb * 8;
                if (diag) {
                    if (j     < gi0)     p0 = 0.0f;
                    if (j + 1 < gi0)     p1 = 0.0f;
                    if (j     < gi0 + 8) p2 = 0.0f;
                    if (j + 1 < gi0 + 8) p3 = 0.0f;
                }
                ls0 += p0 + p1;
                ls1 += p2 + p3;
                *(float2*)(wr0 + nb * 8) = make_float2(p0, p1);
                *(float2*)(wr1 + nb * 8) = make_float2(p2, p3);
                const int e0 = (m0 + ar) * LDE + cb + nb * 8;
                const int e1 = e0 + 8 * LDE;
                *(uint32_t*)(sb + OFF_Q + e0) = pack_h2(p0, p1);
                *(uint32_t*)(sb + OFF_Q + e1) = pack_h2(p2, p3);
            }
            __syncthreads();   // P staged; both halves visible

            // ---- MMA2 (fp16 single product): O += P . V ----
            #pragma unroll
            for (int kb = 0; kb < 8; kb++) {
                uint32_t aP[4];
                ldsm4(aP, su + (uint32_t)((OFF_Q + offA + kb * 16) << 1));
                #pragma unroll
                for (int dbp = 0; dbp < 4; dbp++) {
                    const int dbg = h * 4 + dbp;
                    uint32_t bv[4];
                    ldsm4t(bv, su + (uint32_t)((OFF_V + offV + kb * 16 * LDE + dbg * 16) << 1));
                    mma_f16(Oa[2 * dbp],     aP, bv);
                    mma_f16(Oa[2 * dbp + 1], aP, bv + 2);
                }
            }
        }

        // ---- reduce half-row sums; publish ----
        ls0 += __shfl_xor_sync(0xffffffffu, ls0, 1);
        ls0 += __shfl_xor_sync(0xffffffffu, ls0, 2);
        ls1 += __shfl_xor_sync(0xffffffffu, ls1, 1);
        ls1 += __shfl_xor_sync(0xffffffffu, ls1, 2);
        if (ac == 0) {
            sL[h * 128 + m0 + ar]     = ls0;
            sL[h * 128 + m0 + ar + 8] = ls1;
        }
        __syncthreads();

        const float inv0 = 1.0f / (sL[m0 + ar]     + sL[128 + m0 + ar]);
        const float inv1 = 1.0f / (sL[m0 + ar + 8] + sL[128 + m0 + ar + 8]);

        // ---- store normalized O ----
        float* or0 = outp + ((size_t)(b * SEQ + gi0)) * DIM + h * 64 + 2 * ac;
        float* or1 = or0 + 8 * DIM;
        #pragma unroll
        for (int nb = 0; nb < 8; nb++) {
            *(float2*)(or0 + nb * 8) = make_float2(Oa[nb][0] * inv0, Oa[nb][1] * inv0);
            *(float2*)(or1 + nb * 8) = make_float2(Oa[nb][2] * inv1, Oa[nb][3] * inv1);
        }

        // ---- in-kernel finalize: rescale own rows, cols [i0, SEQ) ----
        {
            const int W1 = (SEQ - i0) / 4;
            for (int row = wid; row < TILE; row += 16) {
                const float inv = 1.0f / (sL[row] + sL[128 + row]);
                float4* wr = (float4*)(wts + ((size_t)(b * SEQ + i0 + row)) * SEQ + i0);
                for (int q = l; q < W1; q += 32) {
                    float4 w = wr[q];
                    w.x *= inv; w.y *= inv; w.z *= inv; w.w *= inv;
                    wr[q] = w;
                }
            }
        }
    }
}

extern "C" void kernel_launch(void* const* d_in, const int* in_sizes, int n_in,
                              void* d_out, int out_size) {
    const float* Q = (const float*)d_in[0];
    const float* K = (const float*)d_in[1];
    const float* V = (const float*)d_in[2];
    float* outp = (float*)d_out;
    float* wts  = outp + (size_t)BATCH * SEQ * DIM;

    dim3 pgrid(NELEM / 4 / 256, 3);
    conv_pre_kernel<<<pgrid, 256>>>(Q, K, V);

    cudaFuncSetAttribute(attn_mma_kernel,
                         cudaFuncAttributeMaxDynamicSharedMemorySize, SMEM_BYTES);
    dim3 grid(9, BATCH);
    attn_mma_kernel<<<grid, 512, SMEM_BYTES>>>(outp, wts);
}

// round 15
// speedup vs baseline: 1.4826x; 1.0226x over previous
#include <cuda_runtime.h>
#include <cuda_bf16.h>
#include <cuda_fp16.h>
#include <cstdint>

#define BATCH 16
#define SEQ   2048
#define DIM   128
#define TILE  128
#define NT    (SEQ/TILE)
#define SCALE 0.088388347648318447f
#define LDE   136                 // 16-bit elements per padded smem row
#define NELEM (BATCH*SEQ*DIM)

#define T_ELEMS (TILE*LDE)
#define OFF_K   0
#define OFF_Q0  (1*T_ELEMS)
#define OFF_Q1  (2*T_ELEMS)
#define OFF_V0  (3*T_ELEMS)
#define OFF_V1  (4*T_ELEMS)
#define OFF_P   (5*T_ELEMS)
#define OFF_SL  (6*T_ELEMS)      // 256 floats: per-half row sums
#define SMEM_BYTES (6*T_ELEMS*2 + 256*4)

// pre-converted fp16 inputs
static __device__ __half g_q16[NELEM];
static __device__ __half g_k16[NELEM];
static __device__ __half g_v16[NELEM];

__device__ __forceinline__ uint32_t smem_u32(const void* p) {
    uint32_t a;
    asm("{ .reg .u64 t; cvta.to.shared.u64 t, %1; cvt.u32.u64 %0, t; }" : "=r"(a) : "l"(p));
    return a;
}
__device__ __forceinline__ void cpa16(uint32_t dst, const void* src) {
    asm volatile("cp.async.cg.shared.global [%0], [%1], 16;" :: "r"(dst), "l"(src));
}
__device__ __forceinline__ void cpa_commit() {
    asm volatile("cp.async.commit_group;" ::: "memory");
}
__device__ __forceinline__ void cpa_wait_all() {
    asm volatile("cp.async.wait_group 0;" ::: "memory");
}
__device__ __forceinline__ void ldsm4(uint32_t* r, uint32_t addr) {
    asm volatile("ldmatrix.sync.aligned.m8n8.x4.shared.b16 {%0,%1,%2,%3}, [%4];"
                 : "=r"(r[0]), "=r"(r[1]), "=r"(r[2]), "=r"(r[3]) : "r"(addr));
}
__device__ __forceinline__ void ldsm4t(uint32_t* r, uint32_t addr) {
    asm volatile("ldmatrix.sync.aligned.m8n8.x4.trans.shared.b16 {%0,%1,%2,%3}, [%4];"
                 : "=r"(r[0]), "=r"(r[1]), "=r"(r[2]), "=r"(r[3]) : "r"(addr));
}
__device__ __forceinline__ void mma_f16(float* d, const uint32_t* a, const uint32_t* b) {
    asm volatile("mma.sync.aligned.m16n8k16.row.col.f32.f16.f16.f32 "
                 "{%0,%1,%2,%3}, {%4,%5,%6,%7}, {%8,%9}, {%0,%1,%2,%3};"
                 : "+f"(d[0]), "+f"(d[1]), "+f"(d[2]), "+f"(d[3])
                 : "r"(a[0]), "r"(a[1]), "r"(a[2]), "r"(a[3]), "r"(b[0]), "r"(b[1]));
}
__device__ __forceinline__ uint32_t pack_h2(float a, float b) {
    __half2 t = __floats2half2_rn(a, b);
    return *(uint32_t*)&t;
}

// ---------------- pre-pass: Q/K/V -> fp16 ----------------
__global__ __launch_bounds__(256)
void conv_pre_kernel(const float* __restrict__ Q, const float* __restrict__ K,
                     const float* __restrict__ V) {
    const int t = blockIdx.y;
    const float* X = (t == 0) ? Q : ((t == 1) ? K : V);
    __half* D = (t == 0) ? g_q16 : ((t == 1) ? g_k16 : g_v16);
    const size_t i4 = (size_t)blockIdx.x * blockDim.x + threadIdx.x;
    const float4 v = ((const float4*)X)[i4];
    __half2 a = __floats2half2_rn(v.x, v.y);
    __half2 b = __floats2half2_rn(v.z, v.w);
    uint2 o; o.x = *(uint32_t*)&a; o.y = *(uint32_t*)&b;
    ((uint2*)D)[i4] = o;
}

// ---------------- main kernel ----------------
__global__ __launch_bounds__(512, 1)
void attn_mma_kernel(float* __restrict__ outp, float* __restrict__ wts) {
    extern __shared__ __align__(16) char smem_raw[];
    __half* sb = (__half*)smem_raw;
    float* sL = (float*)(sb + OFF_SL);      // [2][128]
    const uint32_t su = smem_u32(smem_raw);

    const int tid = threadIdx.x;
    const int wid = tid >> 5;               // 0..15
    const int l   = tid & 31;
    const int m   = wid & 7;
    const int h   = wid >> 3;
    const int m0  = m * 16;
    const int bin = blockIdx.x;             // 0..8
    const int b   = blockIdx.y;

    const int g   = l >> 3, r = l & 7;
    const int gb0 = g & 1, gb1 = g >> 1;
    const int ar  = l >> 2, ac = l & 3;

    const int offA = (m0 + gb0 * 8 + r) * LDE + gb1 * 8;
    const int offB = (gb1 * 8 + r) * LDE + gb0 * 8;
    const int offV = (gb0 * 8 + r) * LDE + gb1 * 8;

    const int crow0 = tid >> 4;             // 0..31
    const int ccol0 = (tid & 15) * 8;

    // 9-bin balanced schedule: bin0 -> {0}; bins1-7 -> {bin, 16-bin}; bin8 -> {8}
    const int itA = (bin == 0) ? 0 : bin;
    const int itB = (bin >= 1 && bin <= 7) ? (16 - bin) : -1;

    #pragma unroll 1
    for (int ph = 0; ph < 2; ph++) {
        const int it = ph ? itB : itA;
        if (it < 0) break;
        const int i0 = it * TILE;
        const int gi0 = i0 + m0 + ar;

        __syncthreads();   // smem reuse across phases

        // ---- prologue: K + Q(buf0) + V(buf0) cp.async ----
        {
            const size_t kbase = (size_t)(b * SEQ + i0) * DIM;
            #pragma unroll
            for (int i = 0; i < 4; i++) {
                const int row = crow0 + i * 32;
                const uint32_t ds = su + (uint32_t)((row * LDE + ccol0) << 1);
                const size_t gofs = kbase + (size_t)row * DIM + ccol0;
                cpa16(ds + (OFF_K << 1),  g_k16 + gofs);
                cpa16(ds + (OFF_Q0 << 1), g_q16 + gofs);
                cpa16(ds + (OFF_V0 << 1), g_v16 + gofs);
            }
            cpa_commit();
        }

        // ---- zero-fill lower-triangle cols [0, i0) (overlaps loads) ----
        {
            const int W0 = i0 / 4;
            const float4 z4 = make_float4(0.0f, 0.0f, 0.0f, 0.0f);
            for (int row = wid; row < TILE; row += 16) {
                float4* wr = (float4*)(wts + ((size_t)(b * SEQ + i0 + row)) * SEQ);
                for (int q = l; q < W0; q += 32) wr[q] = z4;
            }
        }

        float Oa[8][4];
        #pragma unroll
        for (int nb = 0; nb < 8; nb++)
            #pragma unroll
            for (int e = 0; e < 4; e++) Oa[nb][e] = 0.0f;
        float ls0 = 0.0f, ls1 = 0.0f;

        cpa_wait_all();
        __syncthreads();

        #pragma unroll 1
        for (int jt = it; jt < NT; jt++) {
            const int j0 = jt * TILE;
            const int qb = ((jt - it) & 1) ? OFF_Q1 : OFF_Q0;
            const int vb = ((jt - it) & 1) ? OFF_V1 : OFF_V0;

            // ---- MMA1 (fp16): S = K . Q^T ----
            float S[8][4];
            #pragma unroll
            for (int nb = 0; nb < 8; nb++)
                #pragma unroll
                for (int e = 0; e < 4; e++) S[nb][e] = 0.0f;

            #pragma unroll
            for (int ks = 0; ks < 8; ks++) {
                uint32_t ak[4];
                ldsm4(ak, su + (uint32_t)((OFF_K + offA + ks * 16) << 1));
                #pragma unroll
                for (int nbp = 0; nbp < 4; nbp++) {
                    const int nbg = h * 4 + nbp;
                    uint32_t bq[4];
                    ldsm4(bq, su + (uint32_t)((qb + offB + nbg * 16 * LDE + ks * 16) << 1));
                    mma_f16(S[2 * nbp],     ak, bq);
                    mma_f16(S[2 * nbp + 1], ak, bq + 2);
                }
            }
            __syncthreads();   // MMA1 done chip-wide; P buffer free (prev MMA2 done earlier)

            // ---- prefetch next Q/V into other buffers (covered by epilogue+MMA2) ----
            if (jt + 1 < NT) {
                const int qn = (qb == OFF_Q0) ? OFF_Q1 : OFF_Q0;
                const int vn = (vb == OFF_V0) ? OFF_V1 : OFF_V0;
                const size_t base = (size_t)(b * SEQ + j0 + TILE) * DIM;
                #pragma unroll
                for (int i = 0; i < 4; i++) {
                    const int row = crow0 + i * 32;
                    const uint32_t ds = su + (uint32_t)((row * LDE + ccol0) << 1);
                    const size_t gofs = base + (size_t)row * DIM + ccol0;
                    cpa16(ds + (qn << 1), g_q16 + gofs);
                    cpa16(ds + (vn << 1), g_v16 + gofs);
                }
                cpa_commit();
            }

            // ---- epilogue: exp, mask, STG weights, stage P (fp16) ----
            const bool diag = (jt == it);
            const int cb = h * 64 + 2 * ac;
            float* wr0 = wts + ((size_t)(b * SEQ + gi0)) * SEQ + j0 + cb;
            float* wr1 = wr0 + (size_t)8 * SEQ;
            #pragma unroll
            for (int nb = 0; nb < 8; nb++) {
                float p0 = __expf(S[nb][0] * SCALE);
                float p1 = __expf(S[nb][1] * SCALE);
                float p2 = __expf(S[nb][2] * SCALE);
                float p3 = __expf(S[nb][3] * SCALE);
                const int j = j0 + cb + nb * 8;
                if (diag) {
                    if (j     < gi0)     p0 = 0.0f;
                    if (j + 1 < gi0)     p1 = 0.0f;
                    if (j     < gi0 + 8) p2 = 0.0f;
                    if (j + 1 < gi0 + 8) p3 = 0.0f;
                }
                ls0 += p0 + p1;
                ls1 += p2 + p3;
                *(float2*)(wr0 + nb * 8) = make_float2(p0, p1);
                *(float2*)(wr1 + nb * 8) = make_float2(p2, p3);
                const int e0 = (m0 + ar) * LDE + cb + nb * 8;
                const int e1 = e0 + 8 * LDE;
                *(uint32_t*)(sb + OFF_P + e0) = pack_h2(p0, p1);
                *(uint32_t*)(sb + OFF_P + e1) = pack_h2(p2, p3);
            }
            __syncthreads();   // P staged; both halves visible

            // ---- MMA2 (fp16): O += P . V ----
            #pragma unroll
            for (int kb = 0; kb < 8; kb++) {
                uint32_t aP[4];
                ldsm4(aP, su + (uint32_t)((OFF_P + offA + kb * 16) << 1));
                #pragma unroll
                for (int dbp = 0; dbp < 4; dbp++) {
                    const int dbg = h * 4 + dbp;
                    uint32_t bv[4];
                    ldsm4t(bv, su + (uint32_t)((vb + offV + kb * 16 * LDE + dbg * 16) << 1));
                    mma_f16(Oa[2 * dbp],     aP, bv);
                    mma_f16(Oa[2 * dbp + 1], aP, bv + 2);
                }
            }

            if (jt + 1 < NT) cpa_wait_all();   // next tiles landed (should be no-op)
            __syncthreads();   // all MMA2 P/V reads done before next iter's writes
        }

        // ---- reduce half-row sums; publish ----
        ls0 += __shfl_xor_sync(0xffffffffu, ls0, 1);
        ls0 += __shfl_xor_sync(0xffffffffu, ls0, 2);
        ls1 += __shfl_xor_sync(0xffffffffu, ls1, 1);
        ls1 += __shfl_xor_sync(0xffffffffu, ls1, 2);
        if (ac == 0) {
            sL[h * 128 + m0 + ar]     = ls0;
            sL[h * 128 + m0 + ar + 8] = ls1;
        }
        __syncthreads();

        const float inv0 = 1.0f / (sL[m0 + ar]     + sL[128 + m0 + ar]);
        const float inv1 = 1.0f / (sL[m0 + ar + 8] + sL[128 + m0 + ar + 8]);

        // ---- store normalized O ----
        float* or0 = outp + ((size_t)(b * SEQ + gi0)) * DIM + h * 64 + 2 * ac;
        float* or1 = or0 + 8 * DIM;
        #pragma unroll
        for (int nb = 0; nb < 8; nb++) {
            *(float2*)(or0 + nb * 8) = make_float2(Oa[nb][0] * inv0, Oa[nb][1] * inv0);
            *(float2*)(or1 + nb * 8) = make_float2(Oa[nb][2] * inv1, Oa[nb][3] * inv1);
        }

        // ---- in-kernel finalize: rescale own rows, cols [i0, SEQ) ----
        {
            const int W1 = (SEQ - i0) / 4;
            for (int row = wid; row < TILE; row += 16) {
                const float inv = 1.0f / (sL[row] + sL[128 + row]);
                float4* wr = (float4*)(wts + ((size_t)(b * SEQ + i0 + row)) * SEQ + i0);
                for (int q = l; q < W1; q += 32) {
                    float4 w = wr[q];
                    w.x *= inv; w.y *= inv; w.z *= inv; w.w *= inv;
                    wr[q] = w;
                }
            }
        }
    }
}

extern "C" void kernel_launch(void* const* d_in, const int* in_sizes, int n_in,
                              void* d_out, int out_size) {
    const float* Q = (const float*)d_in[0];
    const float* K = (const float*)d_in[1];
    const float* V = (const float*)d_in[2];
    float* outp = (float*)d_out;
    float* wts  = outp + (size_t)BATCH * SEQ * DIM;

    dim3 pgrid(NELEM / 4 / 256, 3);
    conv_pre_kernel<<<pgrid, 256>>>(Q, K, V);

    cudaFuncSetAttribute(attn_mma_kernel,
                         cudaFuncAttributeMaxDynamicSharedMemorySize, SMEM_BYTES);
    dim3 grid(9, BATCH);
    attn_mma_kernel<<<grid, 512, SMEM_BYTES>>>(outp, wts);
}

// round 16
// speedup vs baseline: 1.5041x; 1.0145x over previous
#include <cuda_runtime.h>
#include <cuda_bf16.h>
#include <cuda_fp16.h>
#include <cstdint>

#define BATCH 16
#define SEQ   2048
#define DIM   128
#define TILE  128
#define NT    (SEQ/TILE)
#define SCALE 0.088388347648318447f
#define LDE   136                 // 16-bit elements per padded smem row
#define NELEM (BATCH*SEQ*DIM)

#define T_ELEMS (TILE*LDE)
#define OFF_K   0
#define OFF_Q0  (1*T_ELEMS)
#define OFF_Q1  (2*T_ELEMS)
#define OFF_V0  (3*T_ELEMS)
#define OFF_V1  (4*T_ELEMS)
#define OFF_P   (5*T_ELEMS)
#define OFF_SL  (6*T_ELEMS)      // 256 floats: per-half row sums
#define SMEM_BYTES (6*T_ELEMS*2 + 256*4)

// pre-converted fp16 inputs
static __device__ __half g_q16[NELEM];
static __device__ __half g_k16[NELEM];
static __device__ __half g_v16[NELEM];

__device__ __forceinline__ uint32_t smem_u32(const void* p) {
    uint32_t a;
    asm("{ .reg .u64 t; cvta.to.shared.u64 t, %1; cvt.u32.u64 %0, t; }" : "=r"(a) : "l"(p));
    return a;
}
__device__ __forceinline__ void cpa16(uint32_t dst, const void* src) {
    asm volatile("cp.async.cg.shared.global [%0], [%1], 16;" :: "r"(dst), "l"(src));
}
__device__ __forceinline__ void cpa_commit() {
    asm volatile("cp.async.commit_group;" ::: "memory");
}
__device__ __forceinline__ void cpa_wait_all() {
    asm volatile("cp.async.wait_group 0;" ::: "memory");
}
__device__ __forceinline__ void ldsm4(uint32_t* r, uint32_t addr) {
    asm volatile("ldmatrix.sync.aligned.m8n8.x4.shared.b16 {%0,%1,%2,%3}, [%4];"
                 : "=r"(r[0]), "=r"(r[1]), "=r"(r[2]), "=r"(r[3]) : "r"(addr));
}
__device__ __forceinline__ void ldsm4t(uint32_t* r, uint32_t addr) {
    asm volatile("ldmatrix.sync.aligned.m8n8.x4.trans.shared.b16 {%0,%1,%2,%3}, [%4];"
                 : "=r"(r[0]), "=r"(r[1]), "=r"(r[2]), "=r"(r[3]) : "r"(addr));
}
__device__ __forceinline__ void mma_f16(float* d, const uint32_t* a, const uint32_t* b) {
    asm volatile("mma.sync.aligned.m16n8k16.row.col.f32.f16.f16.f32 "
                 "{%0,%1,%2,%3}, {%4,%5,%6,%7}, {%8,%9}, {%0,%1,%2,%3};"
                 : "+f"(d[0]), "+f"(d[1]), "+f"(d[2]), "+f"(d[3])
                 : "r"(a[0]), "r"(a[1]), "r"(a[2]), "r"(a[3]), "r"(b[0]), "r"(b[1]));
}
__device__ __forceinline__ uint32_t pack_h2(float a, float b) {
    __half2 t = __floats2half2_rn(a, b);
    return *(uint32_t*)&t;
}

// ---------------- pre-pass: Q/K/V -> fp16 ----------------
__global__ __launch_bounds__(256)
void conv_pre_kernel(const float* __restrict__ Q, const float* __restrict__ K,
                     const float* __restrict__ V) {
    const int t = blockIdx.y;
    const float* X = (t == 0) ? Q : ((t == 1) ? K : V);
    __half* D = (t == 0) ? g_q16 : ((t == 1) ? g_k16 : g_v16);
    const size_t i4 = (size_t)blockIdx.x * blockDim.x + threadIdx.x;
    const float4 v = ((const float4*)X)[i4];
    __half2 a = __floats2half2_rn(v.x, v.y);
    __half2 b = __floats2half2_rn(v.z, v.w);
    uint2 o; o.x = *(uint32_t*)&a; o.y = *(uint32_t*)&b;
    ((uint2*)D)[i4] = o;
}

// ---------------- main kernel: merged-MMA pipeline ----------------
__global__ __launch_bounds__(512, 1)
void attn_mma_kernel(float* __restrict__ outp, float* __restrict__ wts) {
    extern __shared__ __align__(16) char smem_raw[];
    __half* sb = (__half*)smem_raw;
    float* sL = (float*)(sb + OFF_SL);      // [2][128]
    const uint32_t su = smem_u32(smem_raw);

    const int tid = threadIdx.x;
    const int wid = tid >> 5;               // 0..15
    const int l   = tid & 31;
    const int m   = wid & 7;
    const int h   = wid >> 3;
    const int m0  = m * 16;
    const int bin = blockIdx.x;             // 0..8
    const int b   = blockIdx.y;

    const int g   = l >> 3, r = l & 7;
    const int gb0 = g & 1, gb1 = g >> 1;
    const int ar  = l >> 2, ac = l & 3;

    const int offA = (m0 + gb0 * 8 + r) * LDE + gb1 * 8;
    const int offB = (gb1 * 8 + r) * LDE + gb0 * 8;
    const int offV = (gb0 * 8 + r) * LDE + gb1 * 8;

    const int crow0 = tid >> 4;             // 0..31
    const int ccol0 = (tid & 15) * 8;

    // 9-bin balanced schedule: bin0 -> {0}; bins1-7 -> {bin, 16-bin}; bin8 -> {8}
    const int itA = (bin == 0) ? 0 : bin;
    const int itB = (bin >= 1 && bin <= 7) ? (16 - bin) : -1;

    #pragma unroll 1
    for (int ph = 0; ph < 2; ph++) {
        const int it = ph ? itB : itA;
        if (it < 0) break;
        const int i0 = it * TILE;
        const int gi0 = i0 + m0 + ar;

        __syncthreads();   // smem reuse across phases

        // ---- prologue: K + Q(buf0) + V(buf0) cp.async ----
        {
            const size_t kbase = (size_t)(b * SEQ + i0) * DIM;
            #pragma unroll
            for (int i = 0; i < 4; i++) {
                const int row = crow0 + i * 32;
                const uint32_t ds = su + (uint32_t)((row * LDE + ccol0) << 1);
                const size_t gofs = kbase + (size_t)row * DIM + ccol0;
                cpa16(ds + (OFF_K << 1),  g_k16 + gofs);
                cpa16(ds + (OFF_Q0 << 1), g_q16 + gofs);
                cpa16(ds + (OFF_V0 << 1), g_v16 + gofs);
            }
            cpa_commit();
        }

        // ---- zero-fill lower-triangle cols [0, i0) (overlaps loads) ----
        {
            const int W0 = i0 / 4;
            const float4 z4 = make_float4(0.0f, 0.0f, 0.0f, 0.0f);
            for (int row = wid; row < TILE; row += 16) {
                float4* wr = (float4*)(wts + ((size_t)(b * SEQ + i0 + row)) * SEQ);
                for (int q = l; q < W0; q += 32) wr[q] = z4;
            }
        }

        float Oa[8][4];
        #pragma unroll
        for (int nb = 0; nb < 8; nb++)
            #pragma unroll
            for (int e = 0; e < 4; e++) Oa[nb][e] = 0.0f;
        float ls0 = 0.0f, ls1 = 0.0f;

        cpa_wait_all();
        __syncthreads();

        #pragma unroll 1
        for (int jt = it; jt < NT; jt++) {
            const int j0 = jt * TILE;
            const int qb = ((jt - it) & 1) ? OFF_Q1 : OFF_Q0;
            const int vp = ((jt - it) & 1) ? OFF_V0 : OFF_V1;   // V of PREVIOUS iter

            // ======== PHASE X: MMA1(jt) + MMA2(jt-1) ========
            float S[8][4];
            #pragma unroll
            for (int nb = 0; nb < 8; nb++)
                #pragma unroll
                for (int e = 0; e < 4; e++) S[nb][e] = 0.0f;

            #pragma unroll
            for (int ks = 0; ks < 8; ks++) {
                uint32_t ak[4];
                ldsm4(ak, su + (uint32_t)((OFF_K + offA + ks * 16) << 1));
                #pragma unroll
                for (int nbp = 0; nbp < 4; nbp++) {
                    const int nbg = h * 4 + nbp;
                    uint32_t bq[4];
                    ldsm4(bq, su + (uint32_t)((qb + offB + nbg * 16 * LDE + ks * 16) << 1));
                    mma_f16(S[2 * nbp],     ak, bq);
                    mma_f16(S[2 * nbp + 1], ak, bq + 2);
                }
            }
            if (jt > it) {
                #pragma unroll
                for (int kb = 0; kb < 8; kb++) {
                    uint32_t aP[4];
                    ldsm4(aP, su + (uint32_t)((OFF_P + offA + kb * 16) << 1));
                    #pragma unroll
                    for (int dbp = 0; dbp < 4; dbp++) {
                        const int dbg = h * 4 + dbp;
                        uint32_t bv[4];
                        ldsm4t(bv, su + (uint32_t)((vp + offV + kb * 16 * LDE + dbg * 16) << 1));
                        mma_f16(Oa[2 * dbp],     aP, bv);
                        mma_f16(Oa[2 * dbp + 1], aP, bv + 2);
                    }
                }
            }
            __syncthreads();   // MMA1+MMA2 reads done: P, V(prev), Q(cur) free for writes

            // ======== PHASE Y: prefetch(jt+1); epilogue(jt) ========
            if (jt + 1 < NT) {
                const int qn = (qb == OFF_Q0) ? OFF_Q1 : OFF_Q0;
                const int vn = vp;                          // prev V buf is free now
                const size_t base = (size_t)(b * SEQ + j0 + TILE) * DIM;
                #pragma unroll
                for (int i = 0; i < 4; i++) {
                    const int row = crow0 + i * 32;
                    const uint32_t ds = su + (uint32_t)((row * LDE + ccol0) << 1);
                    const size_t gofs = base + (size_t)row * DIM + ccol0;
                    cpa16(ds + (qn << 1), g_q16 + gofs);
                    cpa16(ds + (vn << 1), g_v16 + gofs);
                }
                cpa_commit();
            }

            const bool diag = (jt == it);
            const int cb = h * 64 + 2 * ac;
            float* wr0 = wts + ((size_t)(b * SEQ + gi0)) * SEQ + j0 + cb;
            float* wr1 = wr0 + (size_t)8 * SEQ;
            #pragma unroll
            for (int nb = 0; nb < 8; nb++) {
                float p0 = __expf(S[nb][0] * SCALE);
                float p1 = __expf(S[nb][1] * SCALE);
                float p2 = __expf(S[nb][2] * SCALE);
                float p3 = __expf(S[nb][3] * SCALE);
                const int j = j0 + cb + nb * 8;
                if (diag) {
                    if (j     < gi0)     p0 = 0.0f;
                    if (j + 1 < gi0)     p1 = 0.0f;
                    if (j     < gi0 + 8) p2 = 0.0f;
                    if (j + 1 < gi0 + 8) p3 = 0.0f;
                }
                ls0 += p0 + p1;
                ls1 += p2 + p3;
                *(float2*)(wr0 + nb * 8) = make_float2(p0, p1);
                *(float2*)(wr1 + nb * 8) = make_float2(p2, p3);
                const int e0 = (m0 + ar) * LDE + cb + nb * 8;
                const int e1 = e0 + 8 * LDE;
                *(uint32_t*)(sb + OFF_P + e0) = pack_h2(p0, p1);
                *(uint32_t*)(sb + OFF_P + e1) = pack_h2(p2, p3);
            }
            if (jt + 1 < NT) cpa_wait_all();
            __syncthreads();   // P staged + next Q/V landed
        }

        // ---- drain: MMA2(NT-1) ----
        {
            const int vl = ((NT - 1 - it) & 1) ? OFF_V1 : OFF_V0;
            #pragma unroll
            for (int kb = 0; kb < 8; kb++) {
                uint32_t aP[4];
                ldsm4(aP, su + (uint32_t)((OFF_P + offA + kb * 16) << 1));
                #pragma unroll
                for (int dbp = 0; dbp < 4; dbp++) {
                    const int dbg = h * 4 + dbp;
                    uint32_t bv[4];
                    ldsm4t(bv, su + (uint32_t)((vl + offV + kb * 16 * LDE + dbg * 16) << 1));
                    mma_f16(Oa[2 * dbp],     aP, bv);
                    mma_f16(Oa[2 * dbp + 1], aP, bv + 2);
                }
            }
        }

        // ---- reduce half-row sums; publish ----
        ls0 += __shfl_xor_sync(0xffffffffu, ls0, 1);
        ls0 += __shfl_xor_sync(0xffffffffu, ls0, 2);
        ls1 += __shfl_xor_sync(0xffffffffu, ls1, 1);
        ls1 += __shfl_xor_sync(0xffffffffu, ls1, 2);
        if (ac == 0) {
            sL[h * 128 + m0 + ar]     = ls0;
            sL[h * 128 + m0 + ar + 8] = ls1;
        }
        __syncthreads();

        const float inv0 = 1.0f / (sL[m0 + ar]     + sL[128 + m0 + ar]);
        const float inv1 = 1.0f / (sL[m0 + ar + 8] + sL[128 + m0 + ar + 8]);

        // ---- store normalized O ----
        float* or0 = outp + ((size_t)(b * SEQ + gi0)) * DIM + h * 64 + 2 * ac;
        float* or1 = or0 + 8 * DIM;
        #pragma unroll
        for (int nb = 0; nb < 8; nb++) {
            *(float2*)(or0 + nb * 8) = make_float2(Oa[nb][0] * inv0, Oa[nb][1] * inv0);
            *(float2*)(or1 + nb * 8) = make_float2(Oa[nb][2] * inv1, Oa[nb][3] * inv1);
        }

        // ---- in-kernel finalize: rescale own rows, cols [i0, SEQ) ----
        {
            const int W1 = (SEQ - i0) / 4;
            for (int row = wid; row < TILE; row += 16) {
                const float inv = 1.0f / (sL[row] + sL[128 + row]);
                float4* wr = (float4*)(wts + ((size_t)(b * SEQ + i0 + row)) * SEQ + i0);
                for (int q = l; q < W1; q += 32) {
                    float4 w = wr[q];
                    w.x *= inv; w.y *= inv; w.z *= inv; w.w *= inv;
                    wr[q] = w;
                }
            }
        }
    }
}

extern "C" void kernel_launch(void* const* d_in, const int* in_sizes, int n_in,
                              void* d_out, int out_size) {
    const float* Q = (const float*)d_in[0];
    const float* K = (const float*)d_in[1];
    const float* V = (const float*)d_in[2];
    float* outp = (float*)d_out;
    float* wts  = outp + (size_t)BATCH * SEQ * DIM;

    dim3 pgrid(NELEM / 4 / 256, 3);
    conv_pre_kernel<<<pgrid, 256>>>(Q, K, V);

    cudaFuncSetAttribute(attn_mma_kernel,
                         cudaFuncAttributeMaxDynamicSharedMemorySize, SMEM_BYTES);
    dim3 grid(9, BATCH);
    attn_mma_kernel<<<grid, 512, SMEM_BYTES>>>(outp, wts);
}